// round 11
// baseline (speedup 1.0000x reference)
#include <cuda_runtime.h>
#include <cuda_fp16.h>

#define U_N 50000
#define I_N 25000
#define NN  75000
#define DD  64
#define HD  (DD / 2)          // half2 per row = 32
#define EE  2000000
#define BB  4096
#define SCAN_BLK 1024
#define NBLKS ((NN + SCAN_BLK - 1) / SCAN_BLK)   // 74

// Scratch (device globals — no runtime allocation allowed)
__device__ __half2 g_h0[(size_t)NN * HD];   // x0 (fp16)
__device__ __half2 g_h1[(size_t)NN * HD];   // x1
__device__ __half2 g_h2[(size_t)NN * HD];   // x2
__device__ __half2 g_h3[(size_t)NN * HD];   // x3
__device__ int   g_cnt [NN];
__device__ int   g_rowptr[NN + 1];
__device__ int   g_rank[EE];                // rank of edge within its row
__device__ int2  g_edge[EE];                // (col, val-as-int), CSR-ordered
__device__ int   g_bsum[NBLKS];
__device__ int   g_boff[NBLKS];
__device__ int   g_is64;   // 1 if index buffers are int64, 0 if int32

__device__ __forceinline__ int ldidx(const void* __restrict__ p, int i, int is64) {
    if (is64) return (int)((const long long*)p)[i];
    return ((const int*)p)[i];
}

// ---------------------------------------------------------------------------
// Init: x0 = fp16(concat(emb_user, emb_item)); zero counters.
// Block 0 / warp 0 additionally detects the index dtype (int32 vs int64):
// int64 values < 2^31 have all-zero odd 32-bit words.
// ---------------------------------------------------------------------------
__global__ void init_kernel(const float* __restrict__ eu, const float* __restrict__ ei,
                            const void* __restrict__ erow) {
    if (blockIdx.x == 0 && threadIdx.x < 32) {
        const int* w = (const int*)erow;
        int lane = threadIdx.x;
        int any_odd_nonzero = 0;
        for (int i = lane; i < 1024; i += 32)
            if (w[2 * i + 1] != 0) any_odd_nonzero = 1;
        #pragma unroll
        for (int o = 16; o > 0; o >>= 1)
            any_odd_nonzero |= __shfl_xor_sync(0xFFFFFFFFu, any_odd_nonzero, o);
        if (lane == 0) g_is64 = any_odd_nonzero ? 0 : 1;
    }
    int idx = blockIdx.x * blockDim.x + threadIdx.x;
    const int total = NN * HD;
    if (idx < total) {
        int fidx = idx * 2;
        float2 v;
        if (fidx < U_N * DD) {
            v = *(const float2*)(eu + fidx);
        } else {
            v = *(const float2*)(ei + (fidx - U_N * DD));
        }
        g_h0[idx] = __float22half2_rn(v);
    }
    if (idx < NN) g_cnt[idx] = 0;
    if (idx == 0) g_rowptr[NN] = EE;
}

// ---------------------------------------------------------------------------
// CSR build: rank-assigning histogram -> parallel 3-stage scan ->
//            atomic-free scatter (pos = rowptr[row] + rank).
// ---------------------------------------------------------------------------
__global__ void hist_kernel(const void* __restrict__ erow) {
    int i = blockIdx.x * blockDim.x + threadIdx.x;
    int is64 = g_is64;
    if (i < EE) {
        int r = ldidx(erow, i, is64);
        g_rank[i] = atomicAdd(&g_cnt[r], 1);
    }
}

__global__ void scan1_kernel() {
    __shared__ int warp_sums[32];
    int tid  = threadIdx.x;
    int lane = tid & 31;
    int wid  = tid >> 5;
    int i = blockIdx.x * SCAN_BLK + tid;
    int v = (i < NN) ? g_cnt[i] : 0;
    int x = v;
    #pragma unroll
    for (int o = 1; o < 32; o <<= 1) {
        int y = __shfl_up_sync(0xFFFFFFFFu, x, o);
        if (lane >= o) x += y;
    }
    if (lane == 31) warp_sums[wid] = x;
    __syncthreads();
    if (tid < 32) {
        int w = warp_sums[tid];
        #pragma unroll
        for (int o = 1; o < 32; o <<= 1) {
            int y = __shfl_up_sync(0xFFFFFFFFu, w, o);
            if (tid >= o) w += y;
        }
        warp_sums[tid] = w;
    }
    __syncthreads();
    int excl = x - v + (wid > 0 ? warp_sums[wid - 1] : 0);
    if (i < NN) g_rowptr[i] = excl;
    if (tid == SCAN_BLK - 1) g_bsum[blockIdx.x] = excl + v;
}

__global__ void scan2_kernel() {
    __shared__ int ws[4];
    int tid = threadIdx.x, lane = tid & 31, wid = tid >> 5;
    int v = (tid < NBLKS) ? g_bsum[tid] : 0;
    int x = v;
    #pragma unroll
    for (int o = 1; o < 32; o <<= 1) {
        int y = __shfl_up_sync(0xFFFFFFFFu, x, o);
        if (lane >= o) x += y;
    }
    if (lane == 31) ws[wid] = x;
    __syncthreads();
    if (tid == 0) {
        int s = 0;
        #pragma unroll
        for (int k = 0; k < 4; k++) { int t = ws[k]; ws[k] = s; s += t; }
    }
    __syncthreads();
    if (tid < NBLKS) g_boff[tid] = x - v + ws[wid];
}

__global__ void scan3_kernel() {
    int i = blockIdx.x * SCAN_BLK + threadIdx.x;
    if (i < NN)
        g_rowptr[i] += g_boff[blockIdx.x];
}

__global__ void scatter_kernel(const void* __restrict__ erow,
                               const void* __restrict__ ecol,
                               const float* __restrict__ evals) {
    int i = blockIdx.x * blockDim.x + threadIdx.x;
    int is64 = g_is64;
    if (i < EE) {
        int r = ldidx(erow, i, is64);
        int c = ldidx(ecol, i, is64);
        int pos = g_rowptr[r] + g_rank[i];
        g_edge[pos] = make_int2(c, __float_as_int(evals[i]));
    }
}

// ---------------------------------------------------------------------------
// SpMM pass: one warp per row; direct per-lane gather, 4-wide unroll so the
// 4 gathers per iteration are independent and front-batched by ptxas.
// fp16 storage, fp32 accumulate.
// ---------------------------------------------------------------------------
__global__ void spmm_kernel(const __half2* __restrict__ cur, __half2* __restrict__ next) {
    int warp = (blockIdx.x * blockDim.x + threadIdx.x) >> 5;
    if (warp >= NN) return;
    int lane = threadIdx.x & 31;
    int s = g_rowptr[warp];
    int e = g_rowptr[warp + 1];
    float2 a = make_float2(0.f, 0.f);
    int i = s;
    for (; i + 4 <= e; i += 4) {
        int2 e0 = __ldg(&g_edge[i]);
        int2 e1 = __ldg(&g_edge[i + 1]);
        int2 e2 = __ldg(&g_edge[i + 2]);
        int2 e3 = __ldg(&g_edge[i + 3]);
        float2 x0 = __half22float2(__ldg(&cur[(size_t)e0.x * HD + lane]));
        float2 x1 = __half22float2(__ldg(&cur[(size_t)e1.x * HD + lane]));
        float2 x2 = __half22float2(__ldg(&cur[(size_t)e2.x * HD + lane]));
        float2 x3 = __half22float2(__ldg(&cur[(size_t)e3.x * HD + lane]));
        float v0 = __int_as_float(e0.y), v1 = __int_as_float(e1.y);
        float v2 = __int_as_float(e2.y), v3 = __int_as_float(e3.y);
        a.x = fmaf(v0, x0.x, a.x); a.y = fmaf(v0, x0.y, a.y);
        a.x = fmaf(v1, x1.x, a.x); a.y = fmaf(v1, x1.y, a.y);
        a.x = fmaf(v2, x2.x, a.x); a.y = fmaf(v2, x2.y, a.y);
        a.x = fmaf(v3, x3.x, a.x); a.y = fmaf(v3, x3.y, a.y);
    }
    for (; i < e; i++) {
        int2 ev = __ldg(&g_edge[i]);
        float v = __int_as_float(ev.y);
        float2 xv = __half22float2(__ldg(&cur[(size_t)ev.x * HD + lane]));
        a.x = fmaf(v, xv.x, a.x);
        a.y = fmaf(v, xv.y, a.y);
    }
    next[(size_t)warp * HD + lane] = __float22half2_rn(a);
}

// ---------------------------------------------------------------------------
// Epilogue: light_out = (x0+x1+x2+x3)/4 gathered at sampled rows,
// two 64x64 GEMVs, softmax/sigmoid/dot. One warp per batch element.
// ---------------------------------------------------------------------------
__global__ void final_kernel(const float* __restrict__ xij0, const float* __restrict__ xij1,
                             const float* __restrict__ wu,   const float* __restrict__ wi,
                             const void* __restrict__ users,
                             const void* __restrict__ items,
                             const int* __restrict__ xij,
                             float* __restrict__ out) {
    __shared__ float swu[DD * DD];   // swu[d*64 + j] = wu[j*64 + d]
    __shared__ float swi[DD * DD];
    __shared__ float svec[8][2 * DD];

    int tid = threadIdx.x;
    for (int k = tid; k < DD * DD; k += blockDim.x) {
        int j = k / DD, d = k % DD;
        swu[d * DD + j] = wu[k];
        swi[d * DD + j] = wi[k];
    }
    __syncthreads();

    int warp = tid >> 5, lane = tid & 31;
    int b = blockIdx.x * (blockDim.x >> 5) + warp;
    if (b >= BB) return;

    int is64 = g_is64;
    int uu = ldidx(users, b, is64);
    int ii = ldidx(items, b, is64);

    size_t ou = (size_t)uu * HD + lane;          // half2 index
    size_t oi = (size_t)(U_N + ii) * HD + lane;

    float* uv = svec[warp];
    float* iv = svec[warp] + DD;
    {
        float2 s0 = __half22float2(g_h0[ou]);
        float2 s1 = __half22float2(g_h1[ou]);
        float2 s2 = __half22float2(g_h2[ou]);
        float2 s3 = __half22float2(g_h3[ou]);
        uv[lane * 2]     = (s0.x + s1.x + s2.x + s3.x) * 0.25f;
        uv[lane * 2 + 1] = (s0.y + s1.y + s2.y + s3.y) * 0.25f;
        float2 t0 = __half22float2(g_h0[oi]);
        float2 t1 = __half22float2(g_h1[oi]);
        float2 t2 = __half22float2(g_h2[oi]);
        float2 t3 = __half22float2(g_h3[oi]);
        iv[lane * 2]     = (t0.x + t1.x + t2.x + t3.x) * 0.25f;
        iv[lane * 2 + 1] = (t0.y + t1.y + t2.y + t3.y) * 0.25f;
    }
    __syncwarp();

    int j0 = lane, j1 = lane + 32;
    float su0 = 0.f, su1 = 0.f, si0 = 0.f, si1 = 0.f;
    #pragma unroll
    for (int d = 0; d < DD; d++) {
        float ud = uv[d];
        float id = iv[d];
        su0 = fmaf(ud, swu[d * DD + j0], su0);
        su1 = fmaf(ud, swu[d * DD + j1], su1);
        si0 = fmaf(id, swi[d * DD + j0], si0);
        si1 = fmaf(id, swi[d * DD + j1], si1);
    }

    float m = fmaxf(su0, su1);
    #pragma unroll
    for (int o = 16; o > 0; o >>= 1) m = fmaxf(m, __shfl_xor_sync(0xFFFFFFFFu, m, o));
    float e0 = expf(su0 - m), e1 = expf(su1 - m);
    float ssum = e0 + e1;
    #pragma unroll
    for (int o = 16; o > 0; o >>= 1) ssum += __shfl_xor_sync(0xFFFFFFFFu, ssum, o);
    float scale = 0.5f / ssum;   // (1 - HYPER_X) / sum

    float sg0 = 1.f / (1.f + expf(-si0));
    float sg1 = 1.f / (1.f + expf(-si1));
    float part = e0 * scale * sg0 + e1 * scale * sg1;
    #pragma unroll
    for (int o = 16; o > 0; o >>= 1) part += __shfl_xor_sync(0xFFFFFFFFu, part, o);

    if (lane == 0) {
        float xe = xij[b] ? xij1[ii] : xij0[ii];
        float sgx = 1.f / (1.f + expf(-xe));
        out[b] = part + 0.5f * sgx;
    }
}

// ---------------------------------------------------------------------------
extern "C" void kernel_launch(void* const* d_in, const int* in_sizes, int n_in,
                              void* d_out, int out_size) {
    const float* emb_user  = (const float*)d_in[0];
    const float* emb_item  = (const float*)d_in[1];
    const float* xij0      = (const float*)d_in[2];
    const float* xij1      = (const float*)d_in[3];
    const float* w_user    = (const float*)d_in[4];
    const float* w_item    = (const float*)d_in[5];
    const float* edge_vals = (const float*)d_in[6];
    const void*  edge_row  = d_in[7];
    const void*  edge_col  = d_in[8];
    const void*  users     = d_in[9];
    const void*  items     = d_in[10];
    const int*   xij       = (const int*)d_in[11];
    float* out = (float*)d_out;

    __half2 *h0, *h1, *h2, *h3;
    cudaGetSymbolAddress((void**)&h0, g_h0);
    cudaGetSymbolAddress((void**)&h1, g_h1);
    cudaGetSymbolAddress((void**)&h2, g_h2);
    cudaGetSymbolAddress((void**)&h3, g_h3);

    init_kernel<<<(NN * HD + 255) / 256, 256>>>(emb_user, emb_item, edge_row);
    hist_kernel<<<(EE + 255) / 256, 256>>>(edge_row);
    scan1_kernel<<<NBLKS, SCAN_BLK>>>();
    scan2_kernel<<<1, 128>>>();
    scan3_kernel<<<NBLKS, SCAN_BLK>>>();
    scatter_kernel<<<(EE + 255) / 256, 256>>>(edge_row, edge_col, edge_vals);

    const int warps_per_block = 8;
    const int spmm_blocks = (NN + warps_per_block - 1) / warps_per_block;
    spmm_kernel<<<spmm_blocks, 256>>>(h0, h1);
    spmm_kernel<<<spmm_blocks, 256>>>(h1, h2);
    spmm_kernel<<<spmm_blocks, 256>>>(h2, h3);

    final_kernel<<<BB / 8, 256>>>(xij0, xij1, w_user, w_item, users, items, xij, out);
}

// round 12
// speedup vs baseline: 1.0562x; 1.0562x over previous
#include <cuda_runtime.h>
#include <cuda_fp16.h>

#define U_N 50000
#define I_N 25000
#define NN  75000
#define DD  64
#define HD  (DD / 2)          // half2 per row = 32
#define EE  2000000
#define BB  4096
#define SBLK 512
#define SN  ((NN + SBLK - 1) / SBLK)   // 147 blocks (<= 148 SMs: co-resident)

// Scratch (device globals — no runtime allocation allowed).
// g_cnt relies on static zero-init for the first run; the scan kernel
// re-zeroes it after consumption, restoring the invariant for every replay.
__device__ __half2 g_h0[(size_t)NN * HD];
__device__ __half2 g_h1[(size_t)NN * HD];
__device__ __half2 g_h2[(size_t)NN * HD];
__device__ __half2 g_h3[(size_t)NN * HD];
__device__ int   g_cnt [NN];          // zero-initialized
__device__ int   g_rowptr[NN + 1];
__device__ int   g_woff[NN];
__device__ int2  g_edge[EE];
__device__ int   g_bsum[SN];
__device__ int   g_boff[SN];
__device__ int   g_arrive1, g_rel1, g_arrive2, g_rel2;   // zeroed each launch in init_hist

// ---------------------------------------------------------------------------
// Per-block index-dtype detection: int64 values < 2^31 have all-zero odd
// 32-bit words; random int32 indices make that probability ~0.
// Reads words [0, 256) of the buffer (safe: every index buffer >= 16KB).
// ---------------------------------------------------------------------------
__device__ __forceinline__ int block_detect_is64(const void* __restrict__ p) {
    __shared__ int s_is64;
    if (threadIdx.x < 32) {
        const int* w = (const int*)p;
        int nz = 0;
        #pragma unroll
        for (int i = threadIdx.x; i < 128; i += 32)
            nz |= (w[2 * i + 1] != 0);
        #pragma unroll
        for (int o = 16; o > 0; o >>= 1)
            nz |= __shfl_xor_sync(0xFFFFFFFFu, nz, o);
        if (threadIdx.x == 0) s_is64 = nz ? 0 : 1;
    }
    __syncthreads();
    return s_is64;
}

// Load edge pair 2p, 2p+1 as two ints.
__device__ __forceinline__ int2 ldpair(const void* __restrict__ p, int i, int is64) {
    if (is64) {
        longlong2 v = ((const longlong2*)p)[i];
        return make_int2((int)v.x, (int)v.y);
    }
    return ((const int2*)p)[i];
}

// ---------------------------------------------------------------------------
// Kernel 1: init x0 (fp16) + histogram (2 edges/thread) + zero sync state.
// g_cnt is already zero on entry (static init / re-zeroed by scan kernel).
// ---------------------------------------------------------------------------
__global__ void init_hist_kernel(const float* __restrict__ eu, const float* __restrict__ ei,
                                 const void* __restrict__ erow) {
    int is64 = block_detect_is64(erow);
    int idx = blockIdx.x * blockDim.x + threadIdx.x;
    if (idx < NN * HD) {
        int fidx = idx * 2;
        float2 v;
        if (fidx < U_N * DD) v = *(const float2*)(eu + fidx);
        else                 v = *(const float2*)(ei + (fidx - U_N * DD));
        g_h0[idx] = __float22half2_rn(v);
    }
    if (idx == 0) {
        g_rowptr[NN] = EE;
        g_arrive1 = 0; g_rel1 = 0; g_arrive2 = 0; g_rel2 = 0;
    }
    if (idx < EE / 2) {
        int2 r = ldpair(erow, idx, is64);
        atomicAdd(&g_cnt[r.x], 1);
        atomicAdd(&g_cnt[r.y], 1);
    }
}

// ---------------------------------------------------------------------------
// Kernel 2: fused scan (3 stages via elected-block barriers) + scatter.
// 147 blocks x 512 threads, all co-resident -> grid barriers are safe.
// ---------------------------------------------------------------------------
__global__ void __launch_bounds__(SBLK, 1) scan_scatter_kernel(
        const void* __restrict__ erow, const void* __restrict__ ecol,
        const float* __restrict__ evals) {
    __shared__ int sh_w[16];
    __shared__ int sh_bt;       // block total
    __shared__ int sh_elect;
    int b = blockIdx.x, tid = threadIdx.x;
    int lane = tid & 31, wid = tid >> 5;
    int is64 = block_detect_is64(erow);

    // ---- local exclusive scan of g_cnt[b*512 .. ) ----
    int i = b * SBLK + tid;
    int v = (i < NN) ? g_cnt[i] : 0;
    int x = v;
    #pragma unroll
    for (int o = 1; o < 32; o <<= 1) {
        int y = __shfl_up_sync(0xFFFFFFFFu, x, o);
        if (lane >= o) x += y;
    }
    if (lane == 31) sh_w[wid] = x;
    __syncthreads();
    if (tid < 16) {
        int w = sh_w[tid];
        int s = w;
        #pragma unroll
        for (int o = 1; o < 16; o <<= 1) {
            int y = __shfl_up_sync(0xFFFFu, s, o);
            if (tid >= o) s += y;
        }
        sh_w[tid] = s - w;                 // exclusive warp offsets
        if (tid == 15) sh_bt = s;          // block total
    }
    __syncthreads();
    int excl = x - v + sh_w[wid];
    int btotal = sh_bt;

    // ---- publish block total; elect last-arriving block ----
    if (tid == 0) {
        g_bsum[b] = btotal;
        __threadfence();
        int t = atomicAdd(&g_arrive1, 1);
        sh_elect = (t == SN - 1) ? 1 : 0;
    }
    __syncthreads();

    if (sh_elect) {
        // scan the SN block totals (SN=147 <= 512 threads)
        int bv = (tid < SN) ? g_bsum[tid] : 0;
        int bx = bv;
        #pragma unroll
        for (int o = 1; o < 32; o <<= 1) {
            int y = __shfl_up_sync(0xFFFFFFFFu, bx, o);
            if (lane >= o) bx += y;
        }
        __syncthreads();   // sh_w reuse
        if (lane == 31) sh_w[wid] = bx;
        __syncthreads();
        if (tid < 16) {
            int w = sh_w[tid];
            int s = w;
            #pragma unroll
            for (int o = 1; o < 16; o <<= 1) {
                int y = __shfl_up_sync(0xFFFFu, s, o);
                if (tid >= o) s += y;
            }
            sh_w[tid] = s - w;
        }
        __syncthreads();
        if (tid < SN) g_boff[tid] = bx - bv + sh_w[wid];
        __threadfence();
        __syncthreads();
        if (tid == 0) atomicExch(&g_rel1, 1);
    }
    if (tid == 0) { while (atomicAdd(&g_rel1, 0) == 0) { } }
    __syncthreads();
    __threadfence();

    // ---- write final rowptr / write-cursor; re-zero cnt for next launch ----
    int boff = g_boff[b];
    if (i < NN) {
        int r = excl + boff;
        g_rowptr[i] = r;
        g_woff[i]   = r;
        g_cnt[i]    = 0;
    }

    // ---- grid barrier 2 (all rowptr/woff visible) ----
    __threadfence();
    __syncthreads();
    if (tid == 0) {
        int t = atomicAdd(&g_arrive2, 1);
        sh_elect = (t == SN - 1) ? 1 : 0;
    }
    __syncthreads();
    if (sh_elect && tid == 0) atomicExch(&g_rel2, 1);
    if (tid == 0) { while (atomicAdd(&g_rel2, 0) == 0) { } }
    __syncthreads();
    __threadfence();

    // ---- scatter: grid-stride, 2 edges per thread ----
    const int nt = SN * SBLK;
    for (int p = b * SBLK + tid; p < EE / 2; p += nt) {
        int2 r = ldpair(erow, p, is64);
        int2 c = ldpair(ecol, p, is64);
        float2 vv = ((const float2*)evals)[p];
        int pos0 = atomicAdd(&g_woff[r.x], 1);
        g_edge[pos0] = make_int2(c.x, __float_as_int(vv.x));
        int pos1 = atomicAdd(&g_woff[r.y], 1);
        g_edge[pos1] = make_int2(c.y, __float_as_int(vv.y));
    }
}

// ---------------------------------------------------------------------------
// SpMM pass (R9 form — measured best): one warp per row, direct gather,
// fp16 storage, fp32 accumulate.
// ---------------------------------------------------------------------------
__global__ void spmm_kernel(const __half2* __restrict__ cur, __half2* __restrict__ next) {
    int warp = (blockIdx.x * blockDim.x + threadIdx.x) >> 5;
    if (warp >= NN) return;
    int lane = threadIdx.x & 31;
    int s = g_rowptr[warp];
    int e = g_rowptr[warp + 1];
    float2 a = make_float2(0.f, 0.f);
    for (int i = s; i < e; i++) {
        int2 ev = __ldg(&g_edge[i]);
        float v = __int_as_float(ev.y);
        float2 xv = __half22float2(__ldg(&cur[(size_t)ev.x * HD + lane]));
        a.x = fmaf(v, xv.x, a.x);
        a.y = fmaf(v, xv.y, a.y);
    }
    next[(size_t)warp * HD + lane] = __float22half2_rn(a);
}

// ---------------------------------------------------------------------------
// Epilogue: light_out = (x0+x1+x2+x3)/4 at sampled rows, two 64x64 GEMVs,
// softmax/sigmoid/dot. One warp per batch element.
// ---------------------------------------------------------------------------
__global__ void final_kernel(const float* __restrict__ xij0, const float* __restrict__ xij1,
                             const float* __restrict__ wu,   const float* __restrict__ wi,
                             const void* __restrict__ users,
                             const void* __restrict__ items,
                             const int* __restrict__ xij,
                             float* __restrict__ out) {
    __shared__ float swu[DD * DD];   // swu[d*64 + j] = wu[j*64 + d]
    __shared__ float swi[DD * DD];
    __shared__ float svec[8][2 * DD];

    int is64 = block_detect_is64(users);

    int tid = threadIdx.x;
    for (int k = tid; k < DD * DD; k += blockDim.x) {
        int j = k / DD, d = k % DD;
        swu[d * DD + j] = wu[k];
        swi[d * DD + j] = wi[k];
    }
    __syncthreads();

    int warp = tid >> 5, lane = tid & 31;
    int b = blockIdx.x * (blockDim.x >> 5) + warp;
    if (b >= BB) return;

    int uu = is64 ? (int)((const long long*)users)[b] : ((const int*)users)[b];
    int ii = is64 ? (int)((const long long*)items)[b] : ((const int*)items)[b];

    size_t ou = (size_t)uu * HD + lane;
    size_t oi = (size_t)(U_N + ii) * HD + lane;

    float* uv = svec[warp];
    float* iv = svec[warp] + DD;
    {
        float2 s0 = __half22float2(g_h0[ou]);
        float2 s1 = __half22float2(g_h1[ou]);
        float2 s2 = __half22float2(g_h2[ou]);
        float2 s3 = __half22float2(g_h3[ou]);
        uv[lane * 2]     = (s0.x + s1.x + s2.x + s3.x) * 0.25f;
        uv[lane * 2 + 1] = (s0.y + s1.y + s2.y + s3.y) * 0.25f;
        float2 t0 = __half22float2(g_h0[oi]);
        float2 t1 = __half22float2(g_h1[oi]);
        float2 t2 = __half22float2(g_h2[oi]);
        float2 t3 = __half22float2(g_h3[oi]);
        iv[lane * 2]     = (t0.x + t1.x + t2.x + t3.x) * 0.25f;
        iv[lane * 2 + 1] = (t0.y + t1.y + t2.y + t3.y) * 0.25f;
    }
    __syncwarp();

    int j0 = lane, j1 = lane + 32;
    float su0 = 0.f, su1 = 0.f, si0 = 0.f, si1 = 0.f;
    #pragma unroll
    for (int d = 0; d < DD; d++) {
        float ud = uv[d];
        float id = iv[d];
        su0 = fmaf(ud, swu[d * DD + j0], su0);
        su1 = fmaf(ud, swu[d * DD + j1], su1);
        si0 = fmaf(id, swi[d * DD + j0], si0);
        si1 = fmaf(id, swi[d * DD + j1], si1);
    }

    float m = fmaxf(su0, su1);
    #pragma unroll
    for (int o = 16; o > 0; o >>= 1) m = fmaxf(m, __shfl_xor_sync(0xFFFFFFFFu, m, o));
    float e0 = expf(su0 - m), e1 = expf(su1 - m);
    float ssum = e0 + e1;
    #pragma unroll
    for (int o = 16; o > 0; o >>= 1) ssum += __shfl_xor_sync(0xFFFFFFFFu, ssum, o);
    float scale = 0.5f / ssum;   // (1 - HYPER_X) / sum

    float sg0 = 1.f / (1.f + expf(-si0));
    float sg1 = 1.f / (1.f + expf(-si1));
    float part = e0 * scale * sg0 + e1 * scale * sg1;
    #pragma unroll
    for (int o = 16; o > 0; o >>= 1) part += __shfl_xor_sync(0xFFFFFFFFu, part, o);

    if (lane == 0) {
        float xe = xij[b] ? xij1[ii] : xij0[ii];
        float sgx = 1.f / (1.f + expf(-xe));
        out[b] = part + 0.5f * sgx;
    }
}

// ---------------------------------------------------------------------------
extern "C" void kernel_launch(void* const* d_in, const int* in_sizes, int n_in,
                              void* d_out, int out_size) {
    const float* emb_user  = (const float*)d_in[0];
    const float* emb_item  = (const float*)d_in[1];
    const float* xij0      = (const float*)d_in[2];
    const float* xij1      = (const float*)d_in[3];
    const float* w_user    = (const float*)d_in[4];
    const float* w_item    = (const float*)d_in[5];
    const float* edge_vals = (const float*)d_in[6];
    const void*  edge_row  = d_in[7];
    const void*  edge_col  = d_in[8];
    const void*  users     = d_in[9];
    const void*  items     = d_in[10];
    const int*   xij       = (const int*)d_in[11];
    float* out = (float*)d_out;

    __half2 *h0, *h1, *h2, *h3;
    cudaGetSymbolAddress((void**)&h0, g_h0);
    cudaGetSymbolAddress((void**)&h1, g_h1);
    cudaGetSymbolAddress((void**)&h2, g_h2);
    cudaGetSymbolAddress((void**)&h3, g_h3);

    init_hist_kernel<<<(NN * HD + 255) / 256, 256>>>(emb_user, emb_item, edge_row);
    scan_scatter_kernel<<<SN, SBLK>>>(edge_row, edge_col, edge_vals);

    const int spmm_blocks = (NN + 7) / 8;   // 8 warps (rows) per 256-thread block
    spmm_kernel<<<spmm_blocks, 256>>>(h0, h1);
    spmm_kernel<<<spmm_blocks, 256>>>(h1, h2);
    spmm_kernel<<<spmm_blocks, 256>>>(h2, h3);

    final_kernel<<<BB / 8, 256>>>(xij0, xij1, w_user, w_item, users, items, xij, out);
}

// round 16
// speedup vs baseline: 1.1749x; 1.1124x over previous
#include <cuda_runtime.h>
#include <cuda_fp16.h>

#define U_N 50000
#define I_N 25000
#define NN  75000
#define DD  64
#define HD  (DD / 2)          // half2 per row = 32
#define EE  2000000
#define BB  4096
#define SBLK 512
#define SN  ((NN + SBLK - 1) / SBLK)   // 147 blocks (<= 148 SMs: co-resident)

// Scratch (device globals — no runtime allocation allowed).
// g_cnt relies on static zero-init for the first run; the scan kernel
// re-zeroes it after consumption, restoring the invariant for every replay.
__device__ __half2 g_h0[(size_t)NN * HD];
__device__ __half2 g_h1[(size_t)NN * HD];
__device__ __half2 g_h2[(size_t)NN * HD];
__device__ __half2 g_h3[(size_t)NN * HD];
__device__ int   g_cnt [NN];          // zero-initialized
__device__ int   g_rowptr[NN + 1];
__device__ int   g_woff[NN];
__device__ int2  g_edge[EE];
__device__ int   g_bsum[SN];
__device__ int   g_boff[SN];
__device__ int   g_arrive1, g_rel1, g_arrive2, g_rel2;   // zeroed each launch in init_hist

// ---------------------------------------------------------------------------
// Per-block index-dtype detection: int64 values < 2^31 have all-zero odd
// 32-bit words; random int32 indices make that probability ~0.
// ---------------------------------------------------------------------------
__device__ __forceinline__ int block_detect_is64(const void* __restrict__ p) {
    __shared__ int s_is64;
    if (threadIdx.x < 32) {
        const int* w = (const int*)p;
        int nz = 0;
        #pragma unroll
        for (int i = threadIdx.x; i < 128; i += 32)
            nz |= (w[2 * i + 1] != 0);
        #pragma unroll
        for (int o = 16; o > 0; o >>= 1)
            nz |= __shfl_xor_sync(0xFFFFFFFFu, nz, o);
        if (threadIdx.x == 0) s_is64 = nz ? 0 : 1;
    }
    __syncthreads();
    return s_is64;
}

// Load edge pair 2p, 2p+1 as two ints.
__device__ __forceinline__ int2 ldpair(const void* __restrict__ p, int i, int is64) {
    if (is64) {
        longlong2 v = ((const longlong2*)p)[i];
        return make_int2((int)v.x, (int)v.y);
    }
    return ((const int2*)p)[i];
}

// ---------------------------------------------------------------------------
// Kernel 1: init x0 (fp16) + histogram (2 edges/thread) + zero sync state.
// ---------------------------------------------------------------------------
__global__ void init_hist_kernel(const float* __restrict__ eu, const float* __restrict__ ei,
                                 const void* __restrict__ erow) {
    int is64 = block_detect_is64(erow);
    int idx = blockIdx.x * blockDim.x + threadIdx.x;
    if (idx < NN * HD) {
        int fidx = idx * 2;
        float2 v;
        if (fidx < U_N * DD) v = *(const float2*)(eu + fidx);
        else                 v = *(const float2*)(ei + (fidx - U_N * DD));
        g_h0[idx] = __float22half2_rn(v);
    }
    if (idx == 0) {
        g_rowptr[NN] = EE;
        g_arrive1 = 0; g_rel1 = 0; g_arrive2 = 0; g_rel2 = 0;
    }
    if (idx < EE / 2) {
        int2 r = ldpair(erow, idx, is64);
        atomicAdd(&g_cnt[r.x], 1);
        atomicAdd(&g_cnt[r.y], 1);
    }
}

// ---------------------------------------------------------------------------
// Kernel 2: fused scan (3 stages via elected-block barriers) + scatter.
// 147 blocks x 512 threads, all co-resident -> grid barriers are safe.
// ---------------------------------------------------------------------------
__global__ void __launch_bounds__(SBLK, 1) scan_scatter_kernel(
        const void* __restrict__ erow, const void* __restrict__ ecol,
        const float* __restrict__ evals) {
    __shared__ int sh_w[16];
    __shared__ int sh_bt;       // block total
    __shared__ int sh_elect;
    int b = blockIdx.x, tid = threadIdx.x;
    int lane = tid & 31, wid = tid >> 5;
    int is64 = block_detect_is64(erow);

    // ---- local exclusive scan of g_cnt[b*512 .. ) ----
    int i = b * SBLK + tid;
    int v = (i < NN) ? g_cnt[i] : 0;
    int x = v;
    #pragma unroll
    for (int o = 1; o < 32; o <<= 1) {
        int y = __shfl_up_sync(0xFFFFFFFFu, x, o);
        if (lane >= o) x += y;
    }
    if (lane == 31) sh_w[wid] = x;
    __syncthreads();
    if (tid < 16) {
        int w = sh_w[tid];
        int s = w;
        #pragma unroll
        for (int o = 1; o < 16; o <<= 1) {
            int y = __shfl_up_sync(0xFFFFu, s, o);
            if (tid >= o) s += y;
        }
        sh_w[tid] = s - w;                 // exclusive warp offsets
        if (tid == 15) sh_bt = s;          // block total
    }
    __syncthreads();
    int excl = x - v + sh_w[wid];
    int btotal = sh_bt;

    // ---- publish block total; elect last-arriving block ----
    if (tid == 0) {
        g_bsum[b] = btotal;
        __threadfence();
        int t = atomicAdd(&g_arrive1, 1);
        sh_elect = (t == SN - 1) ? 1 : 0;
    }
    __syncthreads();

    if (sh_elect) {
        int bv = (tid < SN) ? g_bsum[tid] : 0;
        int bx = bv;
        #pragma unroll
        for (int o = 1; o < 32; o <<= 1) {
            int y = __shfl_up_sync(0xFFFFFFFFu, bx, o);
            if (lane >= o) bx += y;
        }
        __syncthreads();   // sh_w reuse
        if (lane == 31) sh_w[wid] = bx;
        __syncthreads();
        if (tid < 16) {
            int w = sh_w[tid];
            int s = w;
            #pragma unroll
            for (int o = 1; o < 16; o <<= 1) {
                int y = __shfl_up_sync(0xFFFFu, s, o);
                if (tid >= o) s += y;
            }
            sh_w[tid] = s - w;
        }
        __syncthreads();
        if (tid < SN) g_boff[tid] = bx - bv + sh_w[wid];
        __threadfence();
        __syncthreads();
        if (tid == 0) atomicExch(&g_rel1, 1);
    }
    if (tid == 0) { while (atomicAdd(&g_rel1, 0) == 0) { } }
    __syncthreads();
    __threadfence();

    // ---- write final rowptr / write-cursor; re-zero cnt for next launch ----
    int boff = g_boff[b];
    if (i < NN) {
        int r = excl + boff;
        g_rowptr[i] = r;
        g_woff[i]   = r;
        g_cnt[i]    = 0;
    }

    // ---- grid barrier 2 (all rowptr/woff visible) ----
    __threadfence();
    __syncthreads();
    if (tid == 0) {
        int t = atomicAdd(&g_arrive2, 1);
        sh_elect = (t == SN - 1) ? 1 : 0;
    }
    __syncthreads();
    if (sh_elect && tid == 0) atomicExch(&g_rel2, 1);
    if (tid == 0) { while (atomicAdd(&g_rel2, 0) == 0) { } }
    __syncthreads();
    __threadfence();

    // ---- scatter: grid-stride, 2 edges per thread ----
    const int nt = SN * SBLK;
    for (int p = b * SBLK + tid; p < EE / 2; p += nt) {
        int2 r = ldpair(erow, p, is64);
        int2 c = ldpair(ecol, p, is64);
        float2 vv = ((const float2*)evals)[p];
        int pos0 = atomicAdd(&g_woff[r.x], 1);
        g_edge[pos0] = make_int2(c.x, __float_as_int(vv.x));
        int pos1 = atomicAdd(&g_woff[r.y], 1);
        g_edge[pos1] = make_int2(c.y, __float_as_int(vv.y));
    }
}

// ---------------------------------------------------------------------------
// SpMM pass: one warp per row, 4 edges per iteration.
// Lane layout: grp = lane>>3 picks one of 4 concurrent edges; sub = lane&7
// picks this lane's 16B (8-dim) chunk of the gathered 128B row.
// Per iteration: 1 LDG.64 (4 edges) + 1 LDG.128 (4 row gathers) + 4 cvt +
// 8 FMA -> ~4.5 warp-instr/edge vs ~10 in the scalar form.
// Cross-group reduction via shfl_xor(8,16) once per row.
// ---------------------------------------------------------------------------
__global__ void spmm_kernel(const __half2* __restrict__ cur, __half2* __restrict__ next) {
    int warp = (blockIdx.x * blockDim.x + threadIdx.x) >> 5;
    if (warp >= NN) return;
    int lane = threadIdx.x & 31;
    int grp  = lane >> 3;        // 0..3
    int sub  = lane & 7;         // 0..7
    int s = g_rowptr[warp];
    int e = g_rowptr[warp + 1];

    float a[8];
    #pragma unroll
    for (int k = 0; k < 8; k++) a[k] = 0.f;

    for (int i = s; i < e; i += 4) {
        int idx = i + grp;
        int2 ev = (idx < e) ? __ldg(&g_edge[idx]) : make_int2(0, 0);
        float v = __int_as_float(ev.y);    // 0 for padding -> no-op
        int4 q = __ldg((const int4*)(cur + (size_t)ev.x * HD) + sub);
        __half2* h = (__half2*)&q;
        #pragma unroll
        for (int k = 0; k < 4; k++) {
            float2 f = __half22float2(h[k]);
            a[2 * k]     = fmaf(v, f.x, a[2 * k]);
            a[2 * k + 1] = fmaf(v, f.y, a[2 * k + 1]);
        }
    }

    // reduce the 4 edge-groups (lanes sub, sub+8, sub+16, sub+24)
    #pragma unroll
    for (int k = 0; k < 8; k++) {
        a[k] += __shfl_xor_sync(0xFFFFFFFFu, a[k], 8);
        a[k] += __shfl_xor_sync(0xFFFFFFFFu, a[k], 16);
    }

    if (lane < 8) {
        int4 q;
        __half2* h = (__half2*)&q;
        #pragma unroll
        for (int k = 0; k < 4; k++)
            h[k] = __float22half2_rn(make_float2(a[2 * k], a[2 * k + 1]));
        *((int4*)(next + (size_t)warp * HD) + lane) = q;
    }
}

// ---------------------------------------------------------------------------
// Epilogue: light_out = (x0+x1+x2+x3)/4 at sampled rows, two 64x64 GEMVs,
// softmax/sigmoid/dot. One warp per batch element.
// ---------------------------------------------------------------------------
__global__ void final_kernel(const float* __restrict__ xij0, const float* __restrict__ xij1,
                             const float* __restrict__ wu,   const float* __restrict__ wi,
                             const void* __restrict__ users,
                             const void* __restrict__ items,
                             const int* __restrict__ xij,
                             float* __restrict__ out) {
    __shared__ float swu[DD * DD];   // swu[d*64 + j] = wu[j*64 + d]
    __shared__ float swi[DD * DD];
    __shared__ float svec[8][2 * DD];

    int is64 = block_detect_is64(users);

    int tid = threadIdx.x;
    for (int k = tid; k < DD * DD; k += blockDim.x) {
        int j = k / DD, d = k % DD;
        swu[d * DD + j] = wu[k];
        swi[d * DD + j] = wi[k];
    }
    __syncthreads();

    int warp = tid >> 5, lane = tid & 31;
    int b = blockIdx.x * (blockDim.x >> 5) + warp;
    if (b >= BB) return;

    int uu = is64 ? (int)((const long long*)users)[b] : ((const int*)users)[b];
    int ii = is64 ? (int)((const long long*)items)[b] : ((const int*)items)[b];

    size_t ou = (size_t)uu * HD + lane;
    size_t oi = (size_t)(U_N + ii) * HD + lane;

    float* uv = svec[warp];
    float* iv = svec[warp] + DD;
    {
        float2 s0 = __half22float2(g_h0[ou]);
        float2 s1 = __half22float2(g_h1[ou]);
        float2 s2 = __half22float2(g_h2[ou]);
        float2 s3 = __half22float2(g_h3[ou]);
        uv[lane * 2]     = (s0.x + s1.x + s2.x + s3.x) * 0.25f;
        uv[lane * 2 + 1] = (s0.y + s1.y + s2.y + s3.y) * 0.25f;
        float2 t0 = __half22float2(g_h0[oi]);
        float2 t1 = __half22float2(g_h1[oi]);
        float2 t2 = __half22float2(g_h2[oi]);
        float2 t3 = __half22float2(g_h3[oi]);
        iv[lane * 2]     = (t0.x + t1.x + t2.x + t3.x) * 0.25f;
        iv[lane * 2 + 1] = (t0.y + t1.y + t2.y + t3.y) * 0.25f;
    }
    __syncwarp();

    int j0 = lane, j1 = lane + 32;
    float su0 = 0.f, su1 = 0.f, si0 = 0.f, si1 = 0.f;
    #pragma unroll
    for (int d = 0; d < DD; d++) {
        float ud = uv[d];
        float id = iv[d];
        su0 = fmaf(ud, swu[d * DD + j0], su0);
        su1 = fmaf(ud, swu[d * DD + j1], su1);
        si0 = fmaf(id, swi[d * DD + j0], si0);
        si1 = fmaf(id, swi[d * DD + j1], si1);
    }

    float m = fmaxf(su0, su1);
    #pragma unroll
    for (int o = 16; o > 0; o >>= 1) m = fmaxf(m, __shfl_xor_sync(0xFFFFFFFFu, m, o));
    float e0 = expf(su0 - m), e1 = expf(su1 - m);
    float ssum = e0 + e1;
    #pragma unroll
    for (int o = 16; o > 0; o >>= 1) ssum += __shfl_xor_sync(0xFFFFFFFFu, ssum, o);
    float scale = 0.5f / ssum;   // (1 - HYPER_X) / sum

    float sg0 = 1.f / (1.f + expf(-si0));
    float sg1 = 1.f / (1.f + expf(-si1));
    float part = e0 * scale * sg0 + e1 * scale * sg1;
    #pragma unroll
    for (int o = 16; o > 0; o >>= 1) part += __shfl_xor_sync(0xFFFFFFFFu, part, o);

    if (lane == 0) {
        float xe = xij[b] ? xij1[ii] : xij0[ii];
        float sgx = 1.f / (1.f + expf(-xe));
        out[b] = part + 0.5f * sgx;
    }
}

// ---------------------------------------------------------------------------
extern "C" void kernel_launch(void* const* d_in, const int* in_sizes, int n_in,
                              void* d_out, int out_size) {
    const float* emb_user  = (const float*)d_in[0];
    const float* emb_item  = (const float*)d_in[1];
    const float* xij0      = (const float*)d_in[2];
    const float* xij1      = (const float*)d_in[3];
    const float* w_user    = (const float*)d_in[4];
    const float* w_item    = (const float*)d_in[5];
    const float* edge_vals = (const float*)d_in[6];
    const void*  edge_row  = d_in[7];
    const void*  edge_col  = d_in[8];
    const void*  users     = d_in[9];
    const void*  items     = d_in[10];
    const int*   xij       = (const int*)d_in[11];
    float* out = (float*)d_out;

    __half2 *h0, *h1, *h2, *h3;
    cudaGetSymbolAddress((void**)&h0, g_h0);
    cudaGetSymbolAddress((void**)&h1, g_h1);
    cudaGetSymbolAddress((void**)&h2, g_h2);
    cudaGetSymbolAddress((void**)&h3, g_h3);

    init_hist_kernel<<<(NN * HD + 255) / 256, 256>>>(emb_user, emb_item, edge_row);
    scan_scatter_kernel<<<SN, SBLK>>>(edge_row, edge_col, edge_vals);

    const int spmm_blocks = (NN + 7) / 8;   // 8 warps (rows) per 256-thread block
    spmm_kernel<<<spmm_blocks, 256>>>(h0, h1);
    spmm_kernel<<<spmm_blocks, 256>>>(h1, h2);
    spmm_kernel<<<spmm_blocks, 256>>>(h2, h3);

    final_kernel<<<BB / 8, 256>>>(xij0, xij1, w_user, w_item, users, items, xij, out);
}

// round 17
// speedup vs baseline: 1.1759x; 1.0009x over previous
#include <cuda_runtime.h>
#include <cuda_fp16.h>

#define U_N 50000
#define I_N 25000
#define NN  75000
#define DD  64
#define HD  (DD / 2)          // half2 per row = 32
#define EE  2000000
#define BB  4096
#define SBLK 512
#define SN  ((NN + SBLK - 1) / SBLK)   // 147 blocks (<= 148 SMs: co-resident)

// Scratch (device globals — no runtime allocation allowed).
__device__ __half2 g_h0[(size_t)NN * HD];
__device__ __half2 g_h1[(size_t)NN * HD];
__device__ __half2 g_h2[(size_t)NN * HD];
__device__ __half2 g_h3[(size_t)NN * HD];
__device__ int   g_cnt [NN];          // zero-initialized; re-zeroed each run
__device__ int   g_rowptr[NN + 1];
__device__ int   g_woff[NN];
__device__ int2  g_edge[EE];
__device__ int   g_bsum[SN];
__device__ int   g_boff[SN];
__device__ int   g_arrive1, g_rel1, g_arrive2, g_rel2;

// ---------------------------------------------------------------------------
__device__ __forceinline__ int block_detect_is64(const void* __restrict__ p) {
    __shared__ int s_is64;
    if (threadIdx.x < 32) {
        const int* w = (const int*)p;
        int nz = 0;
        #pragma unroll
        for (int i = threadIdx.x; i < 128; i += 32)
            nz |= (w[2 * i + 1] != 0);
        #pragma unroll
        for (int o = 16; o > 0; o >>= 1)
            nz |= __shfl_xor_sync(0xFFFFFFFFu, nz, o);
        if (threadIdx.x == 0) s_is64 = nz ? 0 : 1;
    }
    __syncthreads();
    return s_is64;
}

__device__ __forceinline__ int2 ldpair(const void* __restrict__ p, int i, int is64) {
    if (is64) {
        longlong2 v = ((const longlong2*)p)[i];
        return make_int2((int)v.x, (int)v.y);
    }
    return ((const int2*)p)[i];
}

// ---------------------------------------------------------------------------
// Kernel 1: init x0 (fp16) + histogram (2 edges/thread) + zero sync state.
// ---------------------------------------------------------------------------
__global__ void init_hist_kernel(const float* __restrict__ eu, const float* __restrict__ ei,
                                 const void* __restrict__ erow) {
    int is64 = block_detect_is64(erow);
    int idx = blockIdx.x * blockDim.x + threadIdx.x;
    if (idx < NN * HD) {
        int fidx = idx * 2;
        float2 v;
        if (fidx < U_N * DD) v = *(const float2*)(eu + fidx);
        else                 v = *(const float2*)(ei + (fidx - U_N * DD));
        g_h0[idx] = __float22half2_rn(v);
    }
    if (idx == 0) {
        g_rowptr[NN] = EE;
        g_arrive1 = 0; g_rel1 = 0; g_arrive2 = 0; g_rel2 = 0;
    }
    if (idx < EE / 2) {
        int2 r = ldpair(erow, idx, is64);
        atomicAdd(&g_cnt[r.x], 1);
        atomicAdd(&g_cnt[r.y], 1);
    }
}

// ---------------------------------------------------------------------------
// Kernel 2: fused scan (3 stages via elected-block barriers) + scatter.
// ---------------------------------------------------------------------------
__global__ void __launch_bounds__(SBLK, 1) scan_scatter_kernel(
        const void* __restrict__ erow, const void* __restrict__ ecol,
        const float* __restrict__ evals) {
    __shared__ int sh_w[16];
    __shared__ int sh_bt;
    __shared__ int sh_elect;
    int b = blockIdx.x, tid = threadIdx.x;
    int lane = tid & 31, wid = tid >> 5;
    int is64 = block_detect_is64(erow);

    int i = b * SBLK + tid;
    int v = (i < NN) ? g_cnt[i] : 0;
    int x = v;
    #pragma unroll
    for (int o = 1; o < 32; o <<= 1) {
        int y = __shfl_up_sync(0xFFFFFFFFu, x, o);
        if (lane >= o) x += y;
    }
    if (lane == 31) sh_w[wid] = x;
    __syncthreads();
    if (tid < 16) {
        int w = sh_w[tid];
        int s = w;
        #pragma unroll
        for (int o = 1; o < 16; o <<= 1) {
            int y = __shfl_up_sync(0xFFFFu, s, o);
            if (tid >= o) s += y;
        }
        sh_w[tid] = s - w;
        if (tid == 15) sh_bt = s;
    }
    __syncthreads();
    int excl = x - v + sh_w[wid];
    int btotal = sh_bt;

    if (tid == 0) {
        g_bsum[b] = btotal;
        __threadfence();
        int t = atomicAdd(&g_arrive1, 1);
        sh_elect = (t == SN - 1) ? 1 : 0;
    }
    __syncthreads();

    if (sh_elect) {
        int bv = (tid < SN) ? g_bsum[tid] : 0;
        int bx = bv;
        #pragma unroll
        for (int o = 1; o < 32; o <<= 1) {
            int y = __shfl_up_sync(0xFFFFFFFFu, bx, o);
            if (lane >= o) bx += y;
        }
        __syncthreads();
        if (lane == 31) sh_w[wid] = bx;
        __syncthreads();
        if (tid < 16) {
            int w = sh_w[tid];
            int s = w;
            #pragma unroll
            for (int o = 1; o < 16; o <<= 1) {
                int y = __shfl_up_sync(0xFFFFu, s, o);
                if (tid >= o) s += y;
            }
            sh_w[tid] = s - w;
        }
        __syncthreads();
        if (tid < SN) g_boff[tid] = bx - bv + sh_w[wid];
        __threadfence();
        __syncthreads();
        if (tid == 0) atomicExch(&g_rel1, 1);
    }
    if (tid == 0) { while (atomicAdd(&g_rel1, 0) == 0) { } }
    __syncthreads();
    __threadfence();

    int boff = g_boff[b];
    if (i < NN) {
        int r = excl + boff;
        g_rowptr[i] = r;
        g_woff[i]   = r;
        g_cnt[i]    = 0;
    }

    __threadfence();
    __syncthreads();
    if (tid == 0) {
        int t = atomicAdd(&g_arrive2, 1);
        sh_elect = (t == SN - 1) ? 1 : 0;
    }
    __syncthreads();
    if (sh_elect && tid == 0) atomicExch(&g_rel2, 1);
    if (tid == 0) { while (atomicAdd(&g_rel2, 0) == 0) { } }
    __syncthreads();
    __threadfence();

    const int nt = SN * SBLK;
    for (int p = b * SBLK + tid; p < EE / 2; p += nt) {
        int2 r = ldpair(erow, p, is64);
        int2 c = ldpair(ecol, p, is64);
        float2 vv = ((const float2*)evals)[p];
        int pos0 = atomicAdd(&g_woff[r.x], 1);
        g_edge[pos0] = make_int2(c.x, __float_as_int(vv.x));
        int pos1 = atomicAdd(&g_woff[r.y], 1);
        g_edge[pos1] = make_int2(c.y, __float_as_int(vv.y));
    }
}

// ---------------------------------------------------------------------------
// SpMM pass: one warp per row, 4 edges/iteration, software-pipelined
// (distance 1): the gather for iteration i+1 is issued BEFORE the FMAs that
// consume iteration i's gather, so each body overlaps one full L2 latency.
// Lane layout: grp = lane>>3 -> edge slot; sub = lane&7 -> 16B row chunk.
// ---------------------------------------------------------------------------
__global__ void spmm_kernel(const __half2* __restrict__ cur, __half2* __restrict__ next) {
    int warp = (blockIdx.x * blockDim.x + threadIdx.x) >> 5;
    if (warp >= NN) return;
    int lane = threadIdx.x & 31;
    int grp  = lane >> 3;        // 0..3
    int sub  = lane & 7;         // 0..7
    int s = g_rowptr[warp];
    int e = g_rowptr[warp + 1];

    float a[8];
    #pragma unroll
    for (int k = 0; k < 8; k++) a[k] = 0.f;

    // prologue: stage 0 loads
    int idx0 = s + grp;
    int2 ev0 = (idx0 < e) ? __ldg(&g_edge[idx0]) : make_int2(0, 0);
    int4 q0  = __ldg((const int4*)(cur + (size_t)ev0.x * HD) + sub);

    for (int i = s; i < e; i += 4) {
        // issue next stage's loads before consuming this stage
        int idxn = i + 4 + grp;
        int2 ev1 = (idxn < e) ? __ldg(&g_edge[idxn]) : make_int2(0, 0);
        int4 q1  = __ldg((const int4*)(cur + (size_t)ev1.x * HD) + sub);

        float v = __int_as_float(ev0.y);   // 0 for padding lanes -> no-op
        __half2* h = (__half2*)&q0;
        #pragma unroll
        for (int k = 0; k < 4; k++) {
            float2 f = __half22float2(h[k]);
            a[2 * k]     = fmaf(v, f.x, a[2 * k]);
            a[2 * k + 1] = fmaf(v, f.y, a[2 * k + 1]);
        }
        ev0 = ev1;
        q0  = q1;
    }

    // reduce the 4 edge-groups (lanes sub, sub+8, sub+16, sub+24)
    #pragma unroll
    for (int k = 0; k < 8; k++) {
        a[k] += __shfl_xor_sync(0xFFFFFFFFu, a[k], 8);
        a[k] += __shfl_xor_sync(0xFFFFFFFFu, a[k], 16);
    }

    if (lane < 8) {
        int4 q;
        __half2* h = (__half2*)&q;
        #pragma unroll
        for (int k = 0; k < 4; k++)
            h[k] = __float22half2_rn(make_float2(a[2 * k], a[2 * k + 1]));
        *((int4*)(next + (size_t)warp * HD) + lane) = q;
    }
}

// ---------------------------------------------------------------------------
// Epilogue: light_out = (x0+x1+x2+x3)/4 at sampled rows, two 64x64 GEMVs,
// softmax/sigmoid/dot. One warp per batch element.
// ---------------------------------------------------------------------------
__global__ void final_kernel(const float* __restrict__ xij0, const float* __restrict__ xij1,
                             const float* __restrict__ wu,   const float* __restrict__ wi,
                             const void* __restrict__ users,
                             const void* __restrict__ items,
                             const int* __restrict__ xij,
                             float* __restrict__ out) {
    __shared__ float swu[DD * DD];
    __shared__ float swi[DD * DD];
    __shared__ float svec[8][2 * DD];

    int is64 = block_detect_is64(users);

    int tid = threadIdx.x;
    for (int k = tid; k < DD * DD; k += blockDim.x) {
        int j = k / DD, d = k % DD;
        swu[d * DD + j] = wu[k];
        swi[d * DD + j] = wi[k];
    }
    __syncthreads();

    int warp = tid >> 5, lane = tid & 31;
    int b = blockIdx.x * (blockDim.x >> 5) + warp;
    if (b >= BB) return;

    int uu = is64 ? (int)((const long long*)users)[b] : ((const int*)users)[b];
    int ii = is64 ? (int)((const long long*)items)[b] : ((const int*)items)[b];

    size_t ou = (size_t)uu * HD + lane;
    size_t oi = (size_t)(U_N + ii) * HD + lane;

    float* uv = svec[warp];
    float* iv = svec[warp] + DD;
    {
        float2 s0 = __half22float2(g_h0[ou]);
        float2 s1 = __half22float2(g_h1[ou]);
        float2 s2 = __half22float2(g_h2[ou]);
        float2 s3 = __half22float2(g_h3[ou]);
        uv[lane * 2]     = (s0.x + s1.x + s2.x + s3.x) * 0.25f;
        uv[lane * 2 + 1] = (s0.y + s1.y + s2.y + s3.y) * 0.25f;
        float2 t0 = __half22float2(g_h0[oi]);
        float2 t1 = __half22float2(g_h1[oi]);
        float2 t2 = __half22float2(g_h2[oi]);
        float2 t3 = __half22float2(g_h3[oi]);
        iv[lane * 2]     = (t0.x + t1.x + t2.x + t3.x) * 0.25f;
        iv[lane * 2 + 1] = (t0.y + t1.y + t2.y + t3.y) * 0.25f;
    }
    __syncwarp();

    int j0 = lane, j1 = lane + 32;
    float su0 = 0.f, su1 = 0.f, si0 = 0.f, si1 = 0.f;
    #pragma unroll
    for (int d = 0; d < DD; d++) {
        float ud = uv[d];
        float id = iv[d];
        su0 = fmaf(ud, swu[d * DD + j0], su0);
        su1 = fmaf(ud, swu[d * DD + j1], su1);
        si0 = fmaf(id, swi[d * DD + j0], si0);
        si1 = fmaf(id, swi[d * DD + j1], si1);
    }

    float m = fmaxf(su0, su1);
    #pragma unroll
    for (int o = 16; o > 0; o >>= 1) m = fmaxf(m, __shfl_xor_sync(0xFFFFFFFFu, m, o));
    float e0 = expf(su0 - m), e1 = expf(su1 - m);
    float ssum = e0 + e1;
    #pragma unroll
    for (int o = 16; o > 0; o >>= 1) ssum += __shfl_xor_sync(0xFFFFFFFFu, ssum, o);
    float scale = 0.5f / ssum;   // (1 - HYPER_X) / sum

    float sg0 = 1.f / (1.f + expf(-si0));
    float sg1 = 1.f / (1.f + expf(-si1));
    float part = e0 * scale * sg0 + e1 * scale * sg1;
    #pragma unroll
    for (int o = 16; o > 0; o >>= 1) part += __shfl_xor_sync(0xFFFFFFFFu, part, o);

    if (lane == 0) {
        float xe = xij[b] ? xij1[ii] : xij0[ii];
        float sgx = 1.f / (1.f + expf(-xe));
        out[b] = part + 0.5f * sgx;
    }
}

// ---------------------------------------------------------------------------
extern "C" void kernel_launch(void* const* d_in, const int* in_sizes, int n_in,
                              void* d_out, int out_size) {
    const float* emb_user  = (const float*)d_in[0];
    const float* emb_item  = (const float*)d_in[1];
    const float* xij0      = (const float*)d_in[2];
    const float* xij1      = (const float*)d_in[3];
    const float* w_user    = (const float*)d_in[4];
    const float* w_item    = (const float*)d_in[5];
    const float* edge_vals = (const float*)d_in[6];
    const void*  edge_row  = d_in[7];
    const void*  edge_col  = d_in[8];
    const void*  users     = d_in[9];
    const void*  items     = d_in[10];
    const int*   xij       = (const int*)d_in[11];
    float* out = (float*)d_out;

    __half2 *h0, *h1, *h2, *h3;
    cudaGetSymbolAddress((void**)&h0, g_h0);
    cudaGetSymbolAddress((void**)&h1, g_h1);
    cudaGetSymbolAddress((void**)&h2, g_h2);
    cudaGetSymbolAddress((void**)&h3, g_h3);

    init_hist_kernel<<<(NN * HD + 255) / 256, 256>>>(emb_user, emb_item, edge_row);
    scan_scatter_kernel<<<SN, SBLK>>>(edge_row, edge_col, edge_vals);

    const int spmm_blocks = (NN + 7) / 8;
    spmm_kernel<<<spmm_blocks, 256>>>(h0, h1);
    spmm_kernel<<<spmm_blocks, 256>>>(h1, h2);
    spmm_kernel<<<spmm_blocks, 256>>>(h2, h3);

    final_kernel<<<BB / 8, 256>>>(xij0, xij1, w_user, w_item, users, items, xij, out);
}